// round 2
// baseline (speedup 1.0000x reference)
#include <cuda_runtime.h>
#include <math.h>

#define N 8192
#define D 32
#define NB 64          // number of 128-blocks
#define B 128          // cholesky block
#define GAMMA 0.03125f
#define REG 1e-3f

// ---------------- device scratch ----------------
__device__ float g_A[(size_t)N * N];          // 256 MB gram / L factor
__device__ float g_invL[(size_t)NB * B * B];  // 4 MB inverses of diag blocks
__device__ float g_xx[N];
__device__ float g_r[N];
__device__ float g_zsol[N];
__device__ float g_alpha[N];
__device__ int   g_ff[NB];
__device__ int   g_fb[NB];

// triangular index decode: p -> (ti, tj), tj <= ti
__device__ __forceinline__ void tri_decode(int p, int& ti, int& tj) {
    float pf = sqrtf(8.f * (float)p + 1.f);
    int i = (int)((pf - 1.f) * 0.5f);
    while ((i + 1) * (i + 2) / 2 <= p) i++;
    while (i * (i + 1) / 2 > p) i--;
    ti = i; tj = p - i * (i + 1) / 2;
}

// ---------------- prep: norms + rhs init + flag reset ----------------
__global__ void prep_kernel(const float* __restrict__ Xtr, const float* __restrict__ y) {
    int i = blockIdx.x * 256 + threadIdx.x;
    float s = 0.f;
#pragma unroll
    for (int dg = 0; dg < 8; dg++) {
        float4 v = *(const float4*)(Xtr + (size_t)i * D + dg * 4);
        s += v.x * v.x + v.y * v.y + v.z * v.z + v.w * v.w;
    }
    g_xx[i] = s;
    g_r[i] = y[i];
    if (i < NB) { g_ff[i] = 0; g_fb[i] = 0; }
}

// ---------------- build gram matrix (lower triangle of blocks) ----------------
__global__ void __launch_bounds__(256, 2) build_kernel(const float* __restrict__ Xtr) {
    __shared__ float sXi[32 * 132];
    __shared__ float sXj[32 * 132];
    __shared__ float sxxi[128], sxxj[128];
    int tid = threadIdx.x;
    int bi, bj;
    tri_decode(blockIdx.x, bi, bj);   // bi >= bj

#pragma unroll
    for (int i = 0; i < 4; i++) {
        int f = tid + i * 256;
        int r = f >> 3;
        int dg = (f & 7) << 2;
        float4 v = *(const float4*)(Xtr + (size_t)(bi * B + r) * D + dg);
        sXi[(dg + 0) * 132 + r] = v.x; sXi[(dg + 1) * 132 + r] = v.y;
        sXi[(dg + 2) * 132 + r] = v.z; sXi[(dg + 3) * 132 + r] = v.w;
        float4 w = *(const float4*)(Xtr + (size_t)(bj * B + r) * D + dg);
        sXj[(dg + 0) * 132 + r] = w.x; sXj[(dg + 1) * 132 + r] = w.y;
        sXj[(dg + 2) * 132 + r] = w.z; sXj[(dg + 3) * 132 + r] = w.w;
    }
    if (tid < 128) { sxxi[tid] = g_xx[bi * B + tid]; sxxj[tid] = g_xx[bj * B + tid]; }
    __syncthreads();

    int tm = tid >> 4, tn = tid & 15;
    float acc[8][8];
#pragma unroll
    for (int i = 0; i < 8; i++)
#pragma unroll
        for (int j = 0; j < 8; j++) acc[i][j] = 0.f;

#pragma unroll
    for (int d = 0; d < 32; d++) {
        float a[8], b[8];
        *(float4*)(a)     = *(const float4*)(&sXi[d * 132 + tm * 8]);
        *(float4*)(a + 4) = *(const float4*)(&sXi[d * 132 + tm * 8 + 4]);
        *(float4*)(b)     = *(const float4*)(&sXj[d * 132 + tn * 8]);
        *(float4*)(b + 4) = *(const float4*)(&sXj[d * 132 + tn * 8 + 4]);
#pragma unroll
        for (int i = 0; i < 8; i++)
#pragma unroll
            for (int j = 0; j < 8; j++) acc[i][j] += a[i] * b[j];
    }

#pragma unroll
    for (int i = 0; i < 8; i++) {
        int li = tm * 8 + i;
        int gi = bi * B + li;
        float v[8];
#pragma unroll
        for (int j = 0; j < 8; j++) {
            int lj = tn * 8 + j;
            int gj = bj * B + lj;
            float sq = sxxi[li] + sxxj[lj] - 2.f * acc[i][j];
            sq = fmaxf(sq, 0.f);
            float val = __expf(-GAMMA * sq);
            if (gi == gj) val += REG;
            v[j] = val;
        }
        float* cp = g_A + (size_t)gi * N + bj * B + tn * 8;
        *(float4*)(cp)     = make_float4(v[0], v[1], v[2], v[3]);
        *(float4*)(cp + 4) = make_float4(v[4], v[5], v[6], v[7]);
    }
}

// ---------------- 128x128x128 tile C (op)= A * B^T (256 thr, 8x8 micro) ----------------
__device__ __forceinline__ void tile_gemm_nt(const float* __restrict__ A, int lda,
                                             const float* __restrict__ Bm, int ldb,
                                             float* __restrict__ C, int ldc, bool sub) {
    __shared__ float As[16 * 132];
    __shared__ float Bs[16 * 132];
    float acc[8][8];
#pragma unroll
    for (int i = 0; i < 8; i++)
#pragma unroll
        for (int j = 0; j < 8; j++) acc[i][j] = 0.f;

    int tid = threadIdx.x;
    int tm = tid >> 4, tn = tid & 15;
    int lr = tid >> 2;
    int lk = (tid & 3) << 2;

    for (int kk = 0; kk < 128; kk += 16) {
#pragma unroll
        for (int h = 0; h < 2; h++) {
            int r = lr + (h << 6);
            float4 va = *(const float4*)(A + (size_t)r * lda + kk + lk);
            As[(lk + 0) * 132 + r] = va.x; As[(lk + 1) * 132 + r] = va.y;
            As[(lk + 2) * 132 + r] = va.z; As[(lk + 3) * 132 + r] = va.w;
            float4 vb = *(const float4*)(Bm + (size_t)r * ldb + kk + lk);
            Bs[(lk + 0) * 132 + r] = vb.x; Bs[(lk + 1) * 132 + r] = vb.y;
            Bs[(lk + 2) * 132 + r] = vb.z; Bs[(lk + 3) * 132 + r] = vb.w;
        }
        __syncthreads();
#pragma unroll
        for (int k = 0; k < 16; k++) {
            float a[8], b[8];
            *(float4*)(a)     = *(const float4*)(&As[k * 132 + tm * 8]);
            *(float4*)(a + 4) = *(const float4*)(&As[k * 132 + tm * 8 + 4]);
            *(float4*)(b)     = *(const float4*)(&Bs[k * 132 + tn * 8]);
            *(float4*)(b + 4) = *(const float4*)(&Bs[k * 132 + tn * 8 + 4]);
#pragma unroll
            for (int i = 0; i < 8; i++)
#pragma unroll
                for (int j = 0; j < 8; j++) acc[i][j] += a[i] * b[j];
        }
        __syncthreads();
    }

#pragma unroll
    for (int i = 0; i < 8; i++) {
        int r = tm * 8 + i;
        float4* cp = (float4*)(C + (size_t)r * ldc + tn * 8);
        if (sub) {
            float4 c0 = cp[0], c1 = cp[1];
            c0.x -= acc[i][0]; c0.y -= acc[i][1]; c0.z -= acc[i][2]; c0.w -= acc[i][3];
            c1.x -= acc[i][4]; c1.y -= acc[i][5]; c1.z -= acc[i][6]; c1.w -= acc[i][7];
            cp[0] = c0; cp[1] = c1;
        } else {
            cp[0] = make_float4(acc[i][0], acc[i][1], acc[i][2], acc[i][3]);
            cp[1] = make_float4(acc[i][4], acc[i][5], acc[i][6], acc[i][7]);
        }
    }
}

// ---------------- panel trsm: 64x128 half-tiles, P := P * W^T ----------------
__global__ void __launch_bounds__(256, 4) trsm_kernel(int kb) {
    __shared__ float As[16 * 68];
    __shared__ float Bs[16 * 132];
    int bx = blockIdx.x;
    int rb = kb + 1 + (bx >> 1);
    int half = bx & 1;
    float* P = g_A + (size_t)(rb * B + half * 64) * N + (size_t)kb * B;
    const float* W = g_invL + (size_t)kb * B * B;
    int tid = threadIdx.x;
    int tm = tid >> 4, tn = tid & 15;
    float acc[4][8];
#pragma unroll
    for (int i = 0; i < 4; i++)
#pragma unroll
        for (int j = 0; j < 8; j++) acc[i][j] = 0.f;
    int lr = tid >> 2;
    int lk = (tid & 3) << 2;

    for (int kk = 0; kk < 128; kk += 16) {
        float4 va = *(const float4*)(P + (size_t)lr * N + kk + lk);
        As[(lk + 0) * 68 + lr] = va.x; As[(lk + 1) * 68 + lr] = va.y;
        As[(lk + 2) * 68 + lr] = va.z; As[(lk + 3) * 68 + lr] = va.w;
#pragma unroll
        for (int h = 0; h < 2; h++) {
            int r = lr + (h << 6);
            float4 vb = *(const float4*)(W + (size_t)r * B + kk + lk);
            Bs[(lk + 0) * 132 + r] = vb.x; Bs[(lk + 1) * 132 + r] = vb.y;
            Bs[(lk + 2) * 132 + r] = vb.z; Bs[(lk + 3) * 132 + r] = vb.w;
        }
        __syncthreads();
#pragma unroll
        for (int k = 0; k < 16; k++) {
            float a[4], b[8];
            *(float4*)(a)     = *(const float4*)(&As[k * 68 + tm * 4]);
            *(float4*)(b)     = *(const float4*)(&Bs[k * 132 + tn * 8]);
            *(float4*)(b + 4) = *(const float4*)(&Bs[k * 132 + tn * 8 + 4]);
#pragma unroll
            for (int i = 0; i < 4; i++)
#pragma unroll
                for (int j = 0; j < 8; j++) acc[i][j] += a[i] * b[j];
        }
        __syncthreads();
    }

#pragma unroll
    for (int i = 0; i < 4; i++) {
        float* cp = P + (size_t)(tm * 4 + i) * N + tn * 8;
        *(float4*)(cp)     = make_float4(acc[i][0], acc[i][1], acc[i][2], acc[i][3]);
        *(float4*)(cp + 4) = make_float4(acc[i][4], acc[i][5], acc[i][6], acc[i][7]);
    }
}

// ---------------- in-smem cholesky + in-place inverse of diag block kb1 ----------------
__device__ void potf_block(int kb1, float* sL) {
    __shared__ float invd[128];
    __shared__ float rowbuf[128];
    int tid = threadIdx.x;
    size_t base = (size_t)(kb1 * B) * N + (size_t)kb1 * B;

    for (int idx = tid; idx < B * B; idx += 256) {
        int r = idx >> 7, c = idx & 127;
        sL[r * 129 + c] = g_A[base + (size_t)r * N + c];
    }
    __syncthreads();

    int tr = tid & 31, tj = tid >> 5;
    for (int c = 0; c < B; c++) {
        float piv = sL[c * 129 + c];
        float inv = rsqrtf(piv);
        if (tid == 0) invd[c] = inv;
        __syncthreads();
        if (tid < B - c) sL[(c + tid) * 129 + c] *= inv;
        __syncthreads();
        if (c < B - 1) {
            for (int r = c + 1 + tr; r < B; r += 32) {
                float lrc = sL[r * 129 + c];
                for (int j = c + 1 + tj; j <= r; j += 8)
                    sL[r * 129 + j] -= lrc * sL[j * 129 + c];
            }
        }
        __syncthreads();
    }

    // in-place inverse: W overwrites strict lower; diag := invd
    for (int c = tid; c < B; c += 256) sL[c * 129 + c] = invd[c];
    __syncthreads();
    for (int r = 1; r < B; r++) {
        for (int c = tid; c < r; c += 256) rowbuf[c] = sL[r * 129 + c];
        __syncthreads();
        if (tid < r) {
            int c = tid;
            float a0 = 0.f, a1 = 0.f, a2 = 0.f, a3 = 0.f;
            int j = c;
            for (; j + 3 < r; j += 4) {
                a0 += rowbuf[j]     * sL[j * 129 + c];
                a1 += rowbuf[j + 1] * sL[(j + 1) * 129 + c];
                a2 += rowbuf[j + 2] * sL[(j + 2) * 129 + c];
                a3 += rowbuf[j + 3] * sL[(j + 3) * 129 + c];
            }
            for (; j < r; j++) a0 += rowbuf[j] * sL[j * 129 + c];
            sL[r * 129 + c] = -invd[r] * ((a0 + a1) + (a2 + a3));
        }
        __syncthreads();
    }

    for (int idx = tid; idx < B * B; idx += 256) {
        int r = idx >> 7, c = idx & 127;
        g_invL[(size_t)kb1 * B * B + idx] = (c <= r) ? sL[r * 129 + c] : 0.f;
    }
}

// ---------------- fused step: block 0 = diag update + potf(kb+1); rest = syrk ----------------
#define STEP_DYN (128 * 129 * 4)
__global__ void __launch_bounds__(256, 2) step_kernel(int kb) {
    extern __shared__ float sL[];
    int kb1 = kb + 1;
    if (blockIdx.x == 0) {
        if (kb >= 0) {
            const float* P = g_A + (size_t)(kb1 * B) * N + (size_t)kb * B;
            float* Cd = g_A + (size_t)(kb1 * B) * N + (size_t)kb1 * B;
            tile_gemm_nt(P, N, P, N, Cd, N, true);
            __syncthreads();
        }
        potf_block(kb1, sL);
    } else {
        int ti, tj;
        tri_decode(blockIdx.x, ti, tj);       // p>=1 excludes (0,0) diag pair
        int ib = kb1 + ti, jb = kb1 + tj;
        tile_gemm_nt(g_A + (size_t)(ib * B) * N + (size_t)kb * B, N,
                     g_A + (size_t)(jb * B) * N + (size_t)kb * B, N,
                     g_A + (size_t)(ib * B) * N + (size_t)jb * B, N, true);
    }
}

// ---------------- spin-chained forward solve:  L z = y ----------------
__global__ void __launch_bounds__(128, 1) fwd_solve() {
    int k = blockIdx.x, t = threadIdx.x;
    __shared__ float svec[128];
    __shared__ float sacc[128];
    float acc = g_r[k * B + t];
    for (int j = 0; j < k; j++) {
        if (t == 0) { while (((volatile int*)g_ff)[j] == 0) __nanosleep(64); }
        __syncthreads();
        __threadfence();
        svec[t] = g_zsol[j * B + t];
        __syncthreads();
        const float* Lr = g_A + (size_t)(k * B + t) * N + (size_t)j * B;
        float a0 = 0.f, a1 = 0.f;
#pragma unroll
        for (int c = 0; c < B; c += 8) {
            float4 l0 = *(const float4*)(Lr + c);
            float4 l1 = *(const float4*)(Lr + c + 4);
            a0 += l0.x * svec[c] + l0.y * svec[c + 1] + l0.z * svec[c + 2] + l0.w * svec[c + 3];
            a1 += l1.x * svec[c + 4] + l1.y * svec[c + 5] + l1.z * svec[c + 6] + l1.w * svec[c + 7];
        }
        acc -= a0 + a1;
        __syncthreads();
    }
    sacc[t] = acc;
    __syncthreads();
    const float* W = g_invL + (size_t)k * B * B;
    float z = 0.f;
#pragma unroll
    for (int c = 0; c < B; c += 4) {
        float4 w = *(const float4*)(W + (size_t)t * B + c);
        z += w.x * sacc[c] + w.y * sacc[c + 1] + w.z * sacc[c + 2] + w.w * sacc[c + 3];
    }
    g_zsol[k * B + t] = z;
    __threadfence();
    __syncthreads();
    if (t == 0) ((volatile int*)g_ff)[k] = 1;
}

// ---------------- spin-chained backward solve:  L^T alpha = z ----------------
__global__ void __launch_bounds__(128, 1) bwd_solve() {
    int k = NB - 1 - blockIdx.x, t = threadIdx.x;
    __shared__ float svec[128];
    __shared__ float sacc[128];
    float acc = g_zsol[k * B + t];
    for (int j = k + 1; j < NB; j++) {
        if (t == 0) { while (((volatile int*)g_fb)[j] == 0) __nanosleep(64); }
        __syncthreads();
        __threadfence();
        svec[t] = g_alpha[j * B + t];
        __syncthreads();
        const float* Lc = g_A + (size_t)(j * B) * N + (size_t)k * B + t;
        float a0 = 0.f, a1 = 0.f, a2 = 0.f, a3 = 0.f;
#pragma unroll 8
        for (int c = 0; c < B; c += 4) {
            a0 += Lc[(size_t)(c + 0) * N] * svec[c + 0];
            a1 += Lc[(size_t)(c + 1) * N] * svec[c + 1];
            a2 += Lc[(size_t)(c + 2) * N] * svec[c + 2];
            a3 += Lc[(size_t)(c + 3) * N] * svec[c + 3];
        }
        acc -= ((a0 + a1) + (a2 + a3));
        __syncthreads();
    }
    sacc[t] = acc;
    __syncthreads();
    const float* W = g_invL + (size_t)k * B * B;
    float al = 0.f;
#pragma unroll 8
    for (int r = 0; r < B; r++) al += W[(size_t)r * B + t] * sacc[r];
    g_alpha[k * B + t] = al;
    __threadfence();
    __syncthreads();
    if (t == 0) ((volatile int*)g_fb)[k] = 1;
}

// ---------------- fused predict ----------------
__global__ void __launch_bounds__(256, 2) predict_kernel(const float* __restrict__ Xte,
                                                         const float* __restrict__ Xtr,
                                                         float* __restrict__ out) {
    __shared__ float sTr[32 * 132];
    __shared__ float sAl[128], sXX[128];
    __shared__ float sRed[256];
    int tid = threadIdx.x;
    int rl = tid >> 3, sl = tid & 7;
    int grow = blockIdx.x * 32 + rl;

    float xt[32];
#pragma unroll
    for (int dg = 0; dg < 8; dg++)
        *(float4*)(xt + dg * 4) = *(const float4*)(Xte + (size_t)grow * D + dg * 4);
    float xxt = 0.f;
#pragma unroll
    for (int d = 0; d < 32; d++) xxt += xt[d] * xt[d];

    float acc = 0.f;
    for (int ch = 0; ch < N / 128; ch++) {
        int pbase = ch * 128;
        __syncthreads();
#pragma unroll
        for (int i = 0; i < 4; i++) {
            int f = tid + i * 256;
            int p = f >> 3;
            int dg = (f & 7) << 2;
            float4 v = *(const float4*)(Xtr + (size_t)(pbase + p) * D + dg);
            sTr[(dg + 0) * 132 + p] = v.x; sTr[(dg + 1) * 132 + p] = v.y;
            sTr[(dg + 2) * 132 + p] = v.z; sTr[(dg + 3) * 132 + p] = v.w;
        }
        if (tid < 128) { sAl[tid] = g_alpha[pbase + tid]; sXX[tid] = g_xx[pbase + tid]; }
        __syncthreads();
#pragma unroll 4
        for (int i = 0; i < 16; i++) {
            int p = i * 8 + sl;
            float dot = 0.f;
#pragma unroll
            for (int d = 0; d < 32; d++) dot += xt[d] * sTr[d * 132 + p];
            float sq = fmaxf(xxt + sXX[p] - 2.f * dot, 0.f);
            acc += __expf(-GAMMA * sq) * sAl[p];
        }
    }
    sRed[rl * 8 + sl] = acc;
    __syncthreads();
    if (tid < 32) {
        float s = 0.f;
#pragma unroll
        for (int j = 0; j < 8; j++) s += sRed[tid * 8 + j];
        out[blockIdx.x * 32 + tid] = s;
    }
}

// ---------------- launcher ----------------
extern "C" void kernel_launch(void* const* d_in, const int* in_sizes, int n_in,
                              void* d_out, int out_size) {
    const float* Xtr = (const float*)d_in[0];
    const float* y   = (const float*)d_in[1];
    const float* Xte = (const float*)d_in[2];
    float* out = (float*)d_out;

    cudaFuncSetAttribute(step_kernel, cudaFuncAttributeMaxDynamicSharedMemorySize, STEP_DYN);

    prep_kernel<<<N / 256, 256>>>(Xtr, y);
    build_kernel<<<NB * (NB + 1) / 2, 256>>>(Xtr);

    step_kernel<<<1, 256, STEP_DYN>>>(-1);   // factor diag block 0

    for (int kb = 0; kb < NB - 1; kb++) {
        int nb = NB - 1 - kb;
        trsm_kernel<<<2 * nb, 256>>>(kb);
        int pairs = nb * (nb + 1) / 2;
        step_kernel<<<pairs, 256, STEP_DYN>>>(kb);  // block0: diag upd + potf(kb+1); rest: syrk
    }

    fwd_solve<<<NB, 128>>>();
    bwd_solve<<<NB, 128>>>();

    predict_kernel<<<N / 32, 256>>>(Xte, Xtr, out);
}

// round 3
// speedup vs baseline: 1.0940x; 1.0940x over previous
#include <cuda_runtime.h>
#include <math.h>

#define N 8192
#define D 32
#define NB 64
#define B 128
#define GAMMA 0.03125f
#define REG 1e-3f
#define NTASK (NB * (NB + 1) / 2)   // 2080
#define GRID_CHOL 296               // 2 CTAs x 148 SMs, co-resident
#define FBASE(j) ((j) * (2 * NB - (j) + 1) / 2)

// ---------------- device scratch ----------------
__device__ float g_A[(size_t)N * N];
__device__ float g_invL[(size_t)NB * B * B];
__device__ float g_xx[N];
__device__ float g_r[N];
__device__ float g_zsol[N];
__device__ float g_alpha[N];
__device__ int   g_tflag[NTASK];   // off-diag tile final
__device__ int   g_dflag[NB];      // invL ready
__device__ int   g_ff[NB];
__device__ int   g_fb[NB];

__device__ __forceinline__ void tri_decode_row(int p, int& ti, int& tj) {
    float pf = sqrtf(8.f * (float)p + 1.f);
    int i = (int)((pf - 1.f) * 0.5f);
    while ((i + 1) * (i + 2) / 2 <= p) i++;
    while (i * (i + 1) / 2 > p) i--;
    ti = i; tj = p - i * (i + 1) / 2;
}

// ---------------- prep ----------------
__global__ void prep_kernel(const float* __restrict__ Xtr, const float* __restrict__ y) {
    int i = blockIdx.x * 256 + threadIdx.x;
    float s = 0.f;
#pragma unroll
    for (int dg = 0; dg < 8; dg++) {
        float4 v = *(const float4*)(Xtr + (size_t)i * D + dg * 4);
        s += v.x * v.x + v.y * v.y + v.z * v.z + v.w * v.w;
    }
    g_xx[i] = s;
    g_r[i] = y[i];
    if (i < NTASK) g_tflag[i] = 0;
    if (i < NB) { g_dflag[i] = 0; g_ff[i] = 0; g_fb[i] = 0; }
}

// ---------------- build gram (lower triangle of 128-blocks) ----------------
__global__ void __launch_bounds__(256, 2) build_kernel(const float* __restrict__ Xtr) {
    __shared__ float sXi[32 * 132];
    __shared__ float sXj[32 * 132];
    __shared__ float sxxi[128], sxxj[128];
    int tid = threadIdx.x;
    int bi, bj;
    tri_decode_row(blockIdx.x, bi, bj);

#pragma unroll
    for (int i = 0; i < 4; i++) {
        int f = tid + i * 256;
        int r = f >> 3;
        int dg = (f & 7) << 2;
        float4 v = *(const float4*)(Xtr + (size_t)(bi * B + r) * D + dg);
        sXi[(dg + 0) * 132 + r] = v.x; sXi[(dg + 1) * 132 + r] = v.y;
        sXi[(dg + 2) * 132 + r] = v.z; sXi[(dg + 3) * 132 + r] = v.w;
        float4 w = *(const float4*)(Xtr + (size_t)(bj * B + r) * D + dg);
        sXj[(dg + 0) * 132 + r] = w.x; sXj[(dg + 1) * 132 + r] = w.y;
        sXj[(dg + 2) * 132 + r] = w.z; sXj[(dg + 3) * 132 + r] = w.w;
    }
    if (tid < 128) { sxxi[tid] = g_xx[bi * B + tid]; sxxj[tid] = g_xx[bj * B + tid]; }
    __syncthreads();

    int tm = tid >> 4, tn = tid & 15;
    float acc[8][8];
#pragma unroll
    for (int i = 0; i < 8; i++)
#pragma unroll
        for (int j = 0; j < 8; j++) acc[i][j] = 0.f;

#pragma unroll
    for (int d = 0; d < 32; d++) {
        float a[8], b[8];
        *(float4*)(a)     = *(const float4*)(&sXi[d * 132 + tm * 8]);
        *(float4*)(a + 4) = *(const float4*)(&sXi[d * 132 + tm * 8 + 4]);
        *(float4*)(b)     = *(const float4*)(&sXj[d * 132 + tn * 8]);
        *(float4*)(b + 4) = *(const float4*)(&sXj[d * 132 + tn * 8 + 4]);
#pragma unroll
        for (int i = 0; i < 8; i++)
#pragma unroll
            for (int j = 0; j < 8; j++) acc[i][j] += a[i] * b[j];
    }

#pragma unroll
    for (int i = 0; i < 8; i++) {
        int li = tm * 8 + i;
        int gi = bi * B + li;
        float v[8];
#pragma unroll
        for (int j = 0; j < 8; j++) {
            int lj = tn * 8 + j;
            int gj = bj * B + lj;
            float sq = sxxi[li] + sxxj[lj] - 2.f * acc[i][j];
            sq = fmaxf(sq, 0.f);
            float val = __expf(-GAMMA * sq);
            if (gi == gj) val += REG;
            v[j] = val;
        }
        float* cp = g_A + (size_t)gi * N + bj * B + tn * 8;
        *(float4*)(cp)     = make_float4(v[0], v[1], v[2], v[3]);
        *(float4*)(cp + 4) = make_float4(v[4], v[5], v[6], v[7]);
    }
}

// ---------------- persistent DAG cholesky ----------------
#define CHOL_DYN (128 * 132 * 4)

__global__ void __launch_bounds__(256, 2) chol_kernel() {
    extern __shared__ float sD[];        // 128x132 staging (also potf @ pitch 129)
    __shared__ float As[16 * 132];
    __shared__ float Bs[16 * 132];
    __shared__ float invd[128];
    __shared__ float rowbuf[128];

    int tid = threadIdx.x;
    int tm = tid >> 4, tn = tid & 15;
    int lr = tid >> 2;
    int lk = (tid & 3) << 2;

    for (int t = blockIdx.x; t < NTASK; t += gridDim.x) {
        // decode column-major triangular index: t -> (i, j), i >= j
        float disc = (2.f * NB + 1.f) * (2.f * NB + 1.f) - 8.f * (float)t;
        int j = (int)((2.f * NB + 1.f - sqrtf(disc)) * 0.5f);
        if (j > NB - 1) j = NB - 1;
        if (j < 0) j = 0;
        while (j < NB - 1 && FBASE(j + 1) <= t) j++;
        while (FBASE(j) > t) j--;
        int i = j + (t - FBASE(j));
        bool diag = (i == j);

        float acc[8][8];
#pragma unroll
        for (int a = 0; a < 8; a++)
#pragma unroll
            for (int b = 0; b < 8; b++) acc[a][b] = 0.f;

        const float* Ai = g_A + (size_t)(i * B) * N;
        const float* Aj = g_A + (size_t)(j * B) * N;

        // ---- left-looking updates: acc += L(i,k) * L(j,k)^T ----
        for (int k = 0; k < j; k++) {
            if (tid == 0) {
                volatile int* tf = (volatile int*)g_tflag;
                while (tf[i * (i + 1) / 2 + k] == 0) __nanosleep(32);
                if (!diag) while (tf[j * (j + 1) / 2 + k] == 0) __nanosleep(32);
            }
            __syncthreads();
            __threadfence();
            const float* Ak = Ai + (size_t)k * B;
            const float* Bk = Aj + (size_t)k * B;

            for (int kk = 0; kk < 128; kk += 16) {
#pragma unroll
                for (int h = 0; h < 2; h++) {
                    int r = lr + (h << 6);
                    float4 va = *(const float4*)(Ak + (size_t)r * N + kk + lk);
                    As[(lk + 0) * 132 + r] = va.x; As[(lk + 1) * 132 + r] = va.y;
                    As[(lk + 2) * 132 + r] = va.z; As[(lk + 3) * 132 + r] = va.w;
                    if (!diag) {
                        float4 vb = *(const float4*)(Bk + (size_t)r * N + kk + lk);
                        Bs[(lk + 0) * 132 + r] = vb.x; Bs[(lk + 1) * 132 + r] = vb.y;
                        Bs[(lk + 2) * 132 + r] = vb.z; Bs[(lk + 3) * 132 + r] = vb.w;
                    }
                }
                __syncthreads();
                const float* Bsrc = diag ? As : Bs;
#pragma unroll
                for (int k2 = 0; k2 < 16; k2++) {
                    float a[8], b[8];
                    *(float4*)(a)     = *(const float4*)(&As[k2 * 132 + tm * 8]);
                    *(float4*)(a + 4) = *(const float4*)(&As[k2 * 132 + tm * 8 + 4]);
                    *(float4*)(b)     = *(const float4*)(&Bsrc[k2 * 132 + tn * 8]);
                    *(float4*)(b + 4) = *(const float4*)(&Bsrc[k2 * 132 + tn * 8 + 4]);
#pragma unroll
                    for (int x = 0; x < 8; x++)
#pragma unroll
                        for (int y = 0; y < 8; y++) acc[x][y] += a[x] * b[y];
                }
                __syncthreads();
            }
        }

        const float* G = g_A + (size_t)(i * B) * N + (size_t)j * B;

        if (diag) {
            // ---- M = gram - acc into sD (pitch 129), then potf + inverse ----
#pragma unroll
            for (int x = 0; x < 8; x++) {
                int r = tm * 8 + x;
#pragma unroll
                for (int y = 0; y < 8; y++) {
                    int c = tn * 8 + y;
                    sD[r * 129 + c] = G[(size_t)r * N + c] - acc[x][y];
                }
            }
            __syncthreads();

            int tr = tid & 31, tj2 = tid >> 5;
            for (int c = 0; c < B; c++) {
                float piv = sD[c * 129 + c];
                float inv = rsqrtf(piv);
                if (tid == 0) invd[c] = inv;
                __syncthreads();
                if (tid < B - c) sD[(c + tid) * 129 + c] *= inv;
                __syncthreads();
                if (c < B - 1) {
                    for (int r = c + 1 + tr; r < B; r += 32) {
                        float lrc = sD[r * 129 + c];
                        for (int jj = c + 1 + tj2; jj <= r; jj += 8)
                            sD[r * 129 + jj] -= lrc * sD[jj * 129 + c];
                    }
                }
                __syncthreads();
            }
            // in-place inverse of L (strict lower overwritten by W, diag = invd)
            for (int c = tid; c < B; c += 256) sD[c * 129 + c] = invd[c];
            __syncthreads();
            for (int r = 1; r < B; r++) {
                for (int c = tid; c < r; c += 256) rowbuf[c] = sD[r * 129 + c];
                __syncthreads();
                if (tid < r) {
                    int c = tid;
                    float a0 = 0.f, a1 = 0.f, a2 = 0.f, a3 = 0.f;
                    int jj = c;
                    for (; jj + 3 < r; jj += 4) {
                        a0 += rowbuf[jj]     * sD[jj * 129 + c];
                        a1 += rowbuf[jj + 1] * sD[(jj + 1) * 129 + c];
                        a2 += rowbuf[jj + 2] * sD[(jj + 2) * 129 + c];
                        a3 += rowbuf[jj + 3] * sD[(jj + 3) * 129 + c];
                    }
                    for (; jj < r; jj++) a0 += rowbuf[jj] * sD[jj * 129 + c];
                    sD[r * 129 + c] = -invd[r] * ((a0 + a1) + (a2 + a3));
                }
                __syncthreads();
            }
            // write invL
            float* Wout = g_invL + (size_t)j * B * B;
            for (int idx = tid; idx < B * B; idx += 256) {
                int r = idx >> 7, c = idx & 127;
                Wout[idx] = (c <= r) ? sD[r * 129 + c] : 0.f;
            }
            __threadfence();
            __syncthreads();
            if (tid == 0) atomicExch(&g_dflag[j], 1);
        } else {
            // ---- stage M^T into sD: sD[c*132 + r] = G[r][c] - acc ----
#pragma unroll
            for (int y = 0; y < 8; y++) {
                int c = tn * 8 + y;
#pragma unroll
                for (int x = 0; x < 8; x++) {
                    int r = tm * 8 + x;
                    sD[c * 132 + r] = G[(size_t)r * N + c] - acc[x][y];
                }
            }
            if (tid == 0) {
                volatile int* df = (volatile int*)g_dflag;
                while (df[j] == 0) __nanosleep(32);
            }
            __syncthreads();
            __threadfence();

            // ---- trsm: out = M * W^T  (W = invL(j)) ----
#pragma unroll
            for (int x = 0; x < 8; x++)
#pragma unroll
                for (int y = 0; y < 8; y++) acc[x][y] = 0.f;

            const float* W = g_invL + (size_t)j * B * B;
            for (int kk = 0; kk < 128; kk += 16) {
#pragma unroll
                for (int h = 0; h < 2; h++) {
                    int r = lr + (h << 6);
                    float4 vb = *(const float4*)(W + (size_t)r * B + kk + lk);
                    Bs[(lk + 0) * 132 + r] = vb.x; Bs[(lk + 1) * 132 + r] = vb.y;
                    Bs[(lk + 2) * 132 + r] = vb.z; Bs[(lk + 3) * 132 + r] = vb.w;
                }
                __syncthreads();
#pragma unroll
                for (int k2 = 0; k2 < 16; k2++) {
                    float a[8], b[8];
                    *(float4*)(a)     = *(const float4*)(&sD[(kk + k2) * 132 + tm * 8]);
                    *(float4*)(a + 4) = *(const float4*)(&sD[(kk + k2) * 132 + tm * 8 + 4]);
                    *(float4*)(b)     = *(const float4*)(&Bs[k2 * 132 + tn * 8]);
                    *(float4*)(b + 4) = *(const float4*)(&Bs[k2 * 132 + tn * 8 + 4]);
#pragma unroll
                    for (int x = 0; x < 8; x++)
#pragma unroll
                        for (int y = 0; y < 8; y++) acc[x][y] += a[x] * b[y];
                }
                __syncthreads();
            }
            float* O = g_A + (size_t)(i * B) * N + (size_t)j * B;
#pragma unroll
            for (int x = 0; x < 8; x++) {
                float* cp = O + (size_t)(tm * 8 + x) * N + tn * 8;
                *(float4*)(cp)     = make_float4(acc[x][0], acc[x][1], acc[x][2], acc[x][3]);
                *(float4*)(cp + 4) = make_float4(acc[x][4], acc[x][5], acc[x][6], acc[x][7]);
            }
            __threadfence();
            __syncthreads();
            if (tid == 0) atomicExch(&g_tflag[i * (i + 1) / 2 + j], 1);
        }
        __syncthreads();
    }
}

// ---------------- spin-chained forward solve ----------------
__global__ void __launch_bounds__(128, 1) fwd_solve() {
    int k = blockIdx.x, t = threadIdx.x;
    __shared__ float svec[128];
    __shared__ float sacc[128];
    float acc = g_r[k * B + t];
    for (int j = 0; j < k; j++) {
        if (t == 0) { while (((volatile int*)g_ff)[j] == 0) __nanosleep(64); }
        __syncthreads();
        __threadfence();
        svec[t] = g_zsol[j * B + t];
        __syncthreads();
        const float* Lr = g_A + (size_t)(k * B + t) * N + (size_t)j * B;
        float a0 = 0.f, a1 = 0.f;
#pragma unroll
        for (int c = 0; c < B; c += 8) {
            float4 l0 = *(const float4*)(Lr + c);
            float4 l1 = *(const float4*)(Lr + c + 4);
            a0 += l0.x * svec[c] + l0.y * svec[c + 1] + l0.z * svec[c + 2] + l0.w * svec[c + 3];
            a1 += l1.x * svec[c + 4] + l1.y * svec[c + 5] + l1.z * svec[c + 6] + l1.w * svec[c + 7];
        }
        acc -= a0 + a1;
        __syncthreads();
    }
    sacc[t] = acc;
    __syncthreads();
    const float* W = g_invL + (size_t)k * B * B;
    float z = 0.f;
#pragma unroll
    for (int c = 0; c < B; c += 4) {
        float4 w = *(const float4*)(W + (size_t)t * B + c);
        z += w.x * sacc[c] + w.y * sacc[c + 1] + w.z * sacc[c + 2] + w.w * sacc[c + 3];
    }
    g_zsol[k * B + t] = z;
    __threadfence();
    __syncthreads();
    if (t == 0) ((volatile int*)g_ff)[k] = 1;
}

// ---------------- spin-chained backward solve ----------------
__global__ void __launch_bounds__(128, 1) bwd_solve() {
    int k = NB - 1 - blockIdx.x, t = threadIdx.x;
    __shared__ float svec[128];
    __shared__ float sacc[128];
    float acc = g_zsol[k * B + t];
    for (int j = k + 1; j < NB; j++) {
        if (t == 0) { while (((volatile int*)g_fb)[j] == 0) __nanosleep(64); }
        __syncthreads();
        __threadfence();
        svec[t] = g_alpha[j * B + t];
        __syncthreads();
        const float* Lc = g_A + (size_t)(j * B) * N + (size_t)k * B + t;
        float a0 = 0.f, a1 = 0.f, a2 = 0.f, a3 = 0.f;
#pragma unroll 8
        for (int c = 0; c < B; c += 4) {
            a0 += Lc[(size_t)(c + 0) * N] * svec[c + 0];
            a1 += Lc[(size_t)(c + 1) * N] * svec[c + 1];
            a2 += Lc[(size_t)(c + 2) * N] * svec[c + 2];
            a3 += Lc[(size_t)(c + 3) * N] * svec[c + 3];
        }
        acc -= ((a0 + a1) + (a2 + a3));
        __syncthreads();
    }
    sacc[t] = acc;
    __syncthreads();
    const float* W = g_invL + (size_t)k * B * B;
    float al = 0.f;
#pragma unroll 8
    for (int r = 0; r < B; r++) al += W[(size_t)r * B + t] * sacc[r];
    g_alpha[k * B + t] = al;
    __threadfence();
    __syncthreads();
    if (t == 0) ((volatile int*)g_fb)[k] = 1;
}

// ---------------- fused predict ----------------
__global__ void __launch_bounds__(256, 2) predict_kernel(const float* __restrict__ Xte,
                                                         const float* __restrict__ Xtr,
                                                         float* __restrict__ out) {
    __shared__ float sTr[32 * 132];
    __shared__ float sAl[128], sXX[128];
    __shared__ float sRed[256];
    int tid = threadIdx.x;
    int rl = tid >> 3, sl = tid & 7;
    int grow = blockIdx.x * 32 + rl;

    float xt[32];
#pragma unroll
    for (int dg = 0; dg < 8; dg++)
        *(float4*)(xt + dg * 4) = *(const float4*)(Xte + (size_t)grow * D + dg * 4);
    float xxt = 0.f;
#pragma unroll
    for (int d = 0; d < 32; d++) xxt += xt[d] * xt[d];

    float acc = 0.f;
    for (int ch = 0; ch < N / 128; ch++) {
        int pbase = ch * 128;
        __syncthreads();
#pragma unroll
        for (int i = 0; i < 4; i++) {
            int f = tid + i * 256;
            int p = f >> 3;
            int dg = (f & 7) << 2;
            float4 v = *(const float4*)(Xtr + (size_t)(pbase + p) * D + dg);
            sTr[(dg + 0) * 132 + p] = v.x; sTr[(dg + 1) * 132 + p] = v.y;
            sTr[(dg + 2) * 132 + p] = v.z; sTr[(dg + 3) * 132 + p] = v.w;
        }
        if (tid < 128) { sAl[tid] = g_alpha[pbase + tid]; sXX[tid] = g_xx[pbase + tid]; }
        __syncthreads();
#pragma unroll 4
        for (int i = 0; i < 16; i++) {
            int p = i * 8 + sl;
            float dot = 0.f;
#pragma unroll
            for (int d = 0; d < 32; d++) dot += xt[d] * sTr[d * 132 + p];
            float sq = fmaxf(xxt + sXX[p] - 2.f * dot, 0.f);
            acc += __expf(-GAMMA * sq) * sAl[p];
        }
    }
    sRed[rl * 8 + sl] = acc;
    __syncthreads();
    if (tid < 32) {
        float s = 0.f;
#pragma unroll
        for (int j = 0; j < 8; j++) s += sRed[tid * 8 + j];
        out[blockIdx.x * 32 + tid] = s;
    }
}

// ---------------- launcher ----------------
extern "C" void kernel_launch(void* const* d_in, const int* in_sizes, int n_in,
                              void* d_out, int out_size) {
    const float* Xtr = (const float*)d_in[0];
    const float* y   = (const float*)d_in[1];
    const float* Xte = (const float*)d_in[2];
    float* out = (float*)d_out;

    cudaFuncSetAttribute(chol_kernel, cudaFuncAttributeMaxDynamicSharedMemorySize, CHOL_DYN);

    prep_kernel<<<N / 256, 256>>>(Xtr, y);
    build_kernel<<<NTASK, 256>>>(Xtr);
    chol_kernel<<<GRID_CHOL, 256, CHOL_DYN>>>();
    fwd_solve<<<NB, 128>>>();
    bwd_solve<<<NB, 128>>>();
    predict_kernel<<<N / 32, 256>>>(Xte, Xtr, out);
}

// round 4
// speedup vs baseline: 1.1237x; 1.0271x over previous
#include <cuda_runtime.h>
#include <math.h>

#define N 8192
#define D 32
#define NB 64
#define B 128
#define GAMMA 0.03125f
#define REG 1e-3f
#define NTASK (NB * (NB + 1) / 2)   // 2080
#define GRID_CHOL 296
#define FBASE(j) ((j) * (2 * NB - (j) + 1) / 2)

// ---------------- device scratch ----------------
__device__ float g_A[(size_t)N * N];
__device__ float g_invL[(size_t)NB * B * B];
__device__ float g_xx[N];
__device__ float g_r[N];
__device__ float g_zsol[N];
__device__ float g_alpha[N];
__device__ int   g_tflag[NTASK];
__device__ int   g_dflag[NB];
__device__ int   g_ff[NB];
__device__ int   g_fb[NB];
__device__ int   g_next;

__device__ __forceinline__ void tri_decode_row(int p, int& ti, int& tj) {
    float pf = sqrtf(8.f * (float)p + 1.f);
    int i = (int)((pf - 1.f) * 0.5f);
    while ((i + 1) * (i + 2) / 2 <= p) i++;
    while (i * (i + 1) / 2 > p) i--;
    ti = i; tj = p - i * (i + 1) / 2;
}

// ---------------- prep ----------------
__global__ void prep_kernel(const float* __restrict__ Xtr, const float* __restrict__ y) {
    int i = blockIdx.x * 256 + threadIdx.x;
    float s = 0.f;
#pragma unroll
    for (int dg = 0; dg < 8; dg++) {
        float4 v = *(const float4*)(Xtr + (size_t)i * D + dg * 4);
        s += v.x * v.x + v.y * v.y + v.z * v.z + v.w * v.w;
    }
    g_xx[i] = s;
    g_r[i] = y[i];
    if (i < NTASK) g_tflag[i] = 0;
    if (i < NB) { g_dflag[i] = 0; g_ff[i] = 0; g_fb[i] = 0; }
    if (i == 0) g_next = 0;
}

// ---------------- build gram (lower triangle of 128-blocks) ----------------
__global__ void __launch_bounds__(256, 2) build_kernel(const float* __restrict__ Xtr) {
    __shared__ float sXi[32 * 132];
    __shared__ float sXj[32 * 132];
    __shared__ float sxxi[128], sxxj[128];
    int tid = threadIdx.x;
    int bi, bj;
    tri_decode_row(blockIdx.x, bi, bj);

#pragma unroll
    for (int i = 0; i < 4; i++) {
        int f = tid + i * 256;
        int r = f >> 3;
        int dg = (f & 7) << 2;
        float4 v = *(const float4*)(Xtr + (size_t)(bi * B + r) * D + dg);
        sXi[(dg + 0) * 132 + r] = v.x; sXi[(dg + 1) * 132 + r] = v.y;
        sXi[(dg + 2) * 132 + r] = v.z; sXi[(dg + 3) * 132 + r] = v.w;
        float4 w = *(const float4*)(Xtr + (size_t)(bj * B + r) * D + dg);
        sXj[(dg + 0) * 132 + r] = w.x; sXj[(dg + 1) * 132 + r] = w.y;
        sXj[(dg + 2) * 132 + r] = w.z; sXj[(dg + 3) * 132 + r] = w.w;
    }
    if (tid < 128) { sxxi[tid] = g_xx[bi * B + tid]; sxxj[tid] = g_xx[bj * B + tid]; }
    __syncthreads();

    int tm = tid >> 4, tn = tid & 15;
    float acc[8][8];
#pragma unroll
    for (int i = 0; i < 8; i++)
#pragma unroll
        for (int j = 0; j < 8; j++) acc[i][j] = 0.f;

#pragma unroll
    for (int d = 0; d < 32; d++) {
        float a[8], b[8];
        *(float4*)(a)     = *(const float4*)(&sXi[d * 132 + tm * 8]);
        *(float4*)(a + 4) = *(const float4*)(&sXi[d * 132 + tm * 8 + 4]);
        *(float4*)(b)     = *(const float4*)(&sXj[d * 132 + tn * 8]);
        *(float4*)(b + 4) = *(const float4*)(&sXj[d * 132 + tn * 8 + 4]);
#pragma unroll
        for (int i = 0; i < 8; i++)
#pragma unroll
            for (int j = 0; j < 8; j++) acc[i][j] += a[i] * b[j];
    }

#pragma unroll
    for (int i = 0; i < 8; i++) {
        int li = tm * 8 + i;
        int gi = bi * B + li;
        float v[8];
#pragma unroll
        for (int j = 0; j < 8; j++) {
            int lj = tn * 8 + j;
            int gj = bj * B + lj;
            float sq = sxxi[li] + sxxj[lj] - 2.f * acc[i][j];
            sq = fmaxf(sq, 0.f);
            float val = __expf(-GAMMA * sq);
            if (gi == gj) val += REG;
            v[j] = val;
        }
        float* cp = g_A + (size_t)gi * N + bj * B + tn * 8;
        *(float4*)(cp)     = make_float4(v[0], v[1], v[2], v[3]);
        *(float4*)(cp + 4) = make_float4(v[4], v[5], v[6], v[7]);
    }
}

// ---------------- persistent DAG cholesky, dynamic work claiming ----------------
#define CHOL_DYN (128 * 132 * 4)

__global__ void __launch_bounds__(256, 2) chol_kernel() {
    extern __shared__ float sD[];
    __shared__ float As[16 * 132];
    __shared__ float Bs[16 * 132];
    __shared__ float invd[128];
    __shared__ float rowbuf[128];
    __shared__ int s_t;

    int tid = threadIdx.x;
    int tm = tid >> 4, tn = tid & 15;
    int lr = tid >> 2;
    int lk = (tid & 3) << 2;

    while (true) {
        if (tid == 0) s_t = atomicAdd(&g_next, 1);
        __syncthreads();
        int t = s_t;
        if (t >= NTASK) break;

        // decode column-major triangular index: t -> (i, j), i >= j
        float disc = (2.f * NB + 1.f) * (2.f * NB + 1.f) - 8.f * (float)t;
        int j = (int)((2.f * NB + 1.f - sqrtf(disc)) * 0.5f);
        if (j > NB - 1) j = NB - 1;
        if (j < 0) j = 0;
        while (j < NB - 1 && FBASE(j + 1) <= t) j++;
        while (FBASE(j) > t) j--;
        int i = j + (t - FBASE(j));
        bool diag = (i == j);

        float acc[8][8];
#pragma unroll
        for (int a = 0; a < 8; a++)
#pragma unroll
            for (int b = 0; b < 8; b++) acc[a][b] = 0.f;

        const float* Ai = g_A + (size_t)(i * B) * N;
        const float* Aj = g_A + (size_t)(j * B) * N;

        // ---- left-looking updates: acc += L(i,k) * L(j,k)^T ----
        for (int k = 0; k < j; k++) {
            if (tid == 0) {
                volatile int* tf = (volatile int*)g_tflag;
                while (tf[i * (i + 1) / 2 + k] == 0) __nanosleep(32);
                if (!diag) while (tf[j * (j + 1) / 2 + k] == 0) __nanosleep(32);
            }
            __syncthreads();
            __threadfence();
            const float* Ak = Ai + (size_t)k * B;
            const float* Bk = Aj + (size_t)k * B;

            for (int kk = 0; kk < 128; kk += 16) {
#pragma unroll
                for (int h = 0; h < 2; h++) {
                    int r = lr + (h << 6);
                    float4 va = *(const float4*)(Ak + (size_t)r * N + kk + lk);
                    As[(lk + 0) * 132 + r] = va.x; As[(lk + 1) * 132 + r] = va.y;
                    As[(lk + 2) * 132 + r] = va.z; As[(lk + 3) * 132 + r] = va.w;
                    if (!diag) {
                        float4 vb = *(const float4*)(Bk + (size_t)r * N + kk + lk);
                        Bs[(lk + 0) * 132 + r] = vb.x; Bs[(lk + 1) * 132 + r] = vb.y;
                        Bs[(lk + 2) * 132 + r] = vb.z; Bs[(lk + 3) * 132 + r] = vb.w;
                    }
                }
                __syncthreads();
                const float* Bsrc = diag ? As : Bs;
#pragma unroll
                for (int k2 = 0; k2 < 16; k2++) {
                    float a[8], b[8];
                    *(float4*)(a)     = *(const float4*)(&As[k2 * 132 + tm * 8]);
                    *(float4*)(a + 4) = *(const float4*)(&As[k2 * 132 + tm * 8 + 4]);
                    *(float4*)(b)     = *(const float4*)(&Bsrc[k2 * 132 + tn * 8]);
                    *(float4*)(b + 4) = *(const float4*)(&Bsrc[k2 * 132 + tn * 8 + 4]);
#pragma unroll
                    for (int x = 0; x < 8; x++)
#pragma unroll
                        for (int y = 0; y < 8; y++) acc[x][y] += a[x] * b[y];
                }
                __syncthreads();
            }
        }

        const float* G = g_A + (size_t)(i * B) * N + (size_t)j * B;

        if (diag) {
            // ---- M = gram - acc into sD (pitch 129) ----
#pragma unroll
            for (int x = 0; x < 8; x++) {
                int r = tm * 8 + x;
#pragma unroll
                for (int y = 0; y < 8; y++) {
                    int c = tn * 8 + y;
                    sD[r * 129 + c] = G[(size_t)r * N + c] - acc[x][y];
                }
            }
            __syncthreads();

            // ---- raw-column cholesky: 1 sync per column ----
            int tr = tid & 31, tj2 = tid >> 5;
            for (int c = 0; c < B - 1; c++) {
                float ipiv = __fdividef(1.f, sD[c * 129 + c]);  // col c frozen
                for (int r = c + 1 + tr; r < B; r += 32) {
                    float a = sD[r * 129 + c] * ipiv;
                    for (int jj = c + 1 + tj2; jj <= r; jj += 8)
                        sD[r * 129 + jj] -= a * sD[jj * 129 + c];
                }
                __syncthreads();
            }
            // finalize: invd + scale columns to L + set diag to invd
            for (int c = tid; c < B; c += 256) invd[c] = rsqrtf(sD[c * 129 + c]);
            __syncthreads();
            for (int idx = tid; idx < B * B; idx += 256) {
                int r = idx >> 7, c = idx & 127;
                if (c < r) sD[r * 129 + c] *= invd[c];
                else if (c == r) sD[r * 129 + c] = invd[c];
            }
            __syncthreads();

            // in-place inverse (strict lower overwritten by W, diag = invd)
            for (int r = 1; r < B; r++) {
                for (int c = tid; c < r; c += 256) rowbuf[c] = sD[r * 129 + c];
                __syncthreads();
                if (tid < r) {
                    int c = tid;
                    float a0 = 0.f, a1 = 0.f, a2 = 0.f, a3 = 0.f;
                    int jj = c;
                    for (; jj + 3 < r; jj += 4) {
                        a0 += rowbuf[jj]     * sD[jj * 129 + c];
                        a1 += rowbuf[jj + 1] * sD[(jj + 1) * 129 + c];
                        a2 += rowbuf[jj + 2] * sD[(jj + 2) * 129 + c];
                        a3 += rowbuf[jj + 3] * sD[(jj + 3) * 129 + c];
                    }
                    for (; jj < r; jj++) a0 += rowbuf[jj] * sD[jj * 129 + c];
                    sD[r * 129 + c] = -invd[r] * ((a0 + a1) + (a2 + a3));
                }
                __syncthreads();
            }
            float* Wout = g_invL + (size_t)j * B * B;
            for (int idx = tid; idx < B * B; idx += 256) {
                int r = idx >> 7, c = idx & 127;
                Wout[idx] = (c <= r) ? sD[r * 129 + c] : 0.f;
            }
            __threadfence();
            __syncthreads();
            if (tid == 0) atomicExch(&g_dflag[j], 1);
        } else {
            // ---- stage M^T into sD ----
#pragma unroll
            for (int y = 0; y < 8; y++) {
                int c = tn * 8 + y;
#pragma unroll
                for (int x = 0; x < 8; x++) {
                    int r = tm * 8 + x;
                    sD[c * 132 + r] = G[(size_t)r * N + c] - acc[x][y];
                }
            }
            if (tid == 0) {
                volatile int* df = (volatile int*)g_dflag;
                while (df[j] == 0) __nanosleep(32);
            }
            __syncthreads();
            __threadfence();

            // ---- trsm: out = M * W^T ----
#pragma unroll
            for (int x = 0; x < 8; x++)
#pragma unroll
                for (int y = 0; y < 8; y++) acc[x][y] = 0.f;

            const float* W = g_invL + (size_t)j * B * B;
            for (int kk = 0; kk < 128; kk += 16) {
#pragma unroll
                for (int h = 0; h < 2; h++) {
                    int r = lr + (h << 6);
                    float4 vb = *(const float4*)(W + (size_t)r * B + kk + lk);
                    Bs[(lk + 0) * 132 + r] = vb.x; Bs[(lk + 1) * 132 + r] = vb.y;
                    Bs[(lk + 2) * 132 + r] = vb.z; Bs[(lk + 3) * 132 + r] = vb.w;
                }
                __syncthreads();
#pragma unroll
                for (int k2 = 0; k2 < 16; k2++) {
                    float a[8], b[8];
                    *(float4*)(a)     = *(const float4*)(&sD[(kk + k2) * 132 + tm * 8]);
                    *(float4*)(a + 4) = *(const float4*)(&sD[(kk + k2) * 132 + tm * 8 + 4]);
                    *(float4*)(b)     = *(const float4*)(&Bs[k2 * 132 + tn * 8]);
                    *(float4*)(b + 4) = *(const float4*)(&Bs[k2 * 132 + tn * 8 + 4]);
#pragma unroll
                    for (int x = 0; x < 8; x++)
#pragma unroll
                        for (int y = 0; y < 8; y++) acc[x][y] += a[x] * b[y];
                }
                __syncthreads();
            }
            float* O = g_A + (size_t)(i * B) * N + (size_t)j * B;
#pragma unroll
            for (int x = 0; x < 8; x++) {
                float* cp = O + (size_t)(tm * 8 + x) * N + tn * 8;
                *(float4*)(cp)     = make_float4(acc[x][0], acc[x][1], acc[x][2], acc[x][3]);
                *(float4*)(cp + 4) = make_float4(acc[x][4], acc[x][5], acc[x][6], acc[x][7]);
            }
            __threadfence();
            __syncthreads();
            if (tid == 0) atomicExch(&g_tflag[i * (i + 1) / 2 + j], 1);
        }
        __syncthreads();
    }
}

// ---------------- spin-chained forward solve (512 thr) ----------------
__global__ void __launch_bounds__(512, 1) fwd_solve() {
    int k = blockIdx.x;
    int tid = threadIdx.x;
    int t = tid & 127, q = tid >> 7;
    __shared__ float svec[128];
    __shared__ float red[512];
    float acc = (q == 0) ? g_r[k * B + t] : 0.f;
    for (int j = 0; j < k; j++) {
        if (tid == 0) { while (((volatile int*)g_ff)[j] == 0) __nanosleep(32); }
        __syncthreads();
        __threadfence();
        if (tid < 128) svec[tid] = g_zsol[j * B + tid];
        __syncthreads();
        const float* Lr = g_A + (size_t)(k * B + t) * N + (size_t)j * B + q * 32;
        float a0 = 0.f, a1 = 0.f;
#pragma unroll
        for (int c = 0; c < 32; c += 8) {
            float4 l0 = *(const float4*)(Lr + c);
            float4 l1 = *(const float4*)(Lr + c + 4);
            int cc = q * 32 + c;
            a0 += l0.x * svec[cc] + l0.y * svec[cc + 1] + l0.z * svec[cc + 2] + l0.w * svec[cc + 3];
            a1 += l1.x * svec[cc + 4] + l1.y * svec[cc + 5] + l1.z * svec[cc + 6] + l1.w * svec[cc + 7];
        }
        acc -= a0 + a1;
        __syncthreads();
    }
    red[q * 128 + t] = acc;
    __syncthreads();
    if (tid < 128) svec[tid] = red[tid] + red[128 + tid] + red[256 + tid] + red[384 + tid];
    __syncthreads();
    // diag apply: z = W * rhs
    const float* Wr = g_invL + (size_t)k * B * B + (size_t)t * B + q * 32;
    float z = 0.f;
#pragma unroll
    for (int c = 0; c < 32; c += 4) {
        float4 w = *(const float4*)(Wr + c);
        int cc = q * 32 + c;
        z += w.x * svec[cc] + w.y * svec[cc + 1] + w.z * svec[cc + 2] + w.w * svec[cc + 3];
    }
    red[q * 128 + t] = z;
    __syncthreads();
    if (tid < 128) g_zsol[k * B + tid] = red[tid] + red[128 + tid] + red[256 + tid] + red[384 + tid];
    __threadfence();
    __syncthreads();
    if (tid == 0) atomicExch(&g_ff[k], 1);
}

// ---------------- spin-chained backward solve (512 thr) ----------------
__global__ void __launch_bounds__(512, 1) bwd_solve() {
    int k = NB - 1 - blockIdx.x;
    int tid = threadIdx.x;
    int t = tid & 127, q = tid >> 7;
    __shared__ float svec[128];
    __shared__ float red[512];
    float acc = (q == 0) ? g_zsol[k * B + t] : 0.f;
    for (int j = k + 1; j < NB; j++) {
        if (tid == 0) { while (((volatile int*)g_fb)[j] == 0) __nanosleep(32); }
        __syncthreads();
        __threadfence();
        if (tid < 128) svec[tid] = g_alpha[j * B + tid];
        __syncthreads();
        const float* Lc = g_A + (size_t)(j * B + q * 32) * N + (size_t)k * B + t;
        float a0 = 0.f, a1 = 0.f, a2 = 0.f, a3 = 0.f;
#pragma unroll
        for (int r = 0; r < 32; r += 4) {
            int rr = q * 32 + r;
            a0 += Lc[(size_t)(r + 0) * N] * svec[rr + 0];
            a1 += Lc[(size_t)(r + 1) * N] * svec[rr + 1];
            a2 += Lc[(size_t)(r + 2) * N] * svec[rr + 2];
            a3 += Lc[(size_t)(r + 3) * N] * svec[rr + 3];
        }
        acc -= ((a0 + a1) + (a2 + a3));
        __syncthreads();
    }
    red[q * 128 + t] = acc;
    __syncthreads();
    if (tid < 128) svec[tid] = red[tid] + red[128 + tid] + red[256 + tid] + red[384 + tid];
    __syncthreads();
    // diag apply: alpha = W^T * rhs
    const float* Wc = g_invL + (size_t)k * B * B + (size_t)(q * 32) * B + t;
    float al = 0.f;
#pragma unroll 8
    for (int r = 0; r < 32; r++) al += Wc[(size_t)r * B] * svec[q * 32 + r];
    red[q * 128 + t] = al;
    __syncthreads();
    if (tid < 128) g_alpha[k * B + tid] = red[tid] + red[128 + tid] + red[256 + tid] + red[384 + tid];
    __threadfence();
    __syncthreads();
    if (tid == 0) atomicExch(&g_fb[k], 1);
}

// ---------------- fused predict ----------------
__global__ void __launch_bounds__(256, 2) predict_kernel(const float* __restrict__ Xte,
                                                         const float* __restrict__ Xtr,
                                                         float* __restrict__ out) {
    __shared__ float sTr[32 * 132];
    __shared__ float sAl[128], sXX[128];
    __shared__ float sRed[256];
    int tid = threadIdx.x;
    int rl = tid >> 3, sl = tid & 7;
    int grow = blockIdx.x * 32 + rl;

    float xt[32];
#pragma unroll
    for (int dg = 0; dg < 8; dg++)
        *(float4*)(xt + dg * 4) = *(const float4*)(Xte + (size_t)grow * D + dg * 4);
    float xxt = 0.f;
#pragma unroll
    for (int d = 0; d < 32; d++) xxt += xt[d] * xt[d];

    float acc = 0.f;
    for (int ch = 0; ch < N / 128; ch++) {
        int pbase = ch * 128;
        __syncthreads();
#pragma unroll
        for (int i = 0; i < 4; i++) {
            int f = tid + i * 256;
            int p = f >> 3;
            int dg = (f & 7) << 2;
            float4 v = *(const float4*)(Xtr + (size_t)(pbase + p) * D + dg);
            sTr[(dg + 0) * 132 + p] = v.x; sTr[(dg + 1) * 132 + p] = v.y;
            sTr[(dg + 2) * 132 + p] = v.z; sTr[(dg + 3) * 132 + p] = v.w;
        }
        if (tid < 128) { sAl[tid] = g_alpha[pbase + tid]; sXX[tid] = g_xx[pbase + tid]; }
        __syncthreads();
#pragma unroll 4
        for (int i = 0; i < 16; i++) {
            int p = i * 8 + sl;
            float dot = 0.f;
#pragma unroll
            for (int d = 0; d < 32; d++) dot += xt[d] * sTr[d * 132 + p];
            float sq = fmaxf(xxt + sXX[p] - 2.f * dot, 0.f);
            acc += __expf(-GAMMA * sq) * sAl[p];
        }
    }
    sRed[rl * 8 + sl] = acc;
    __syncthreads();
    if (tid < 32) {
        float s = 0.f;
#pragma unroll
        for (int j = 0; j < 8; j++) s += sRed[tid * 8 + j];
        out[blockIdx.x * 32 + tid] = s;
    }
}

// ---------------- launcher ----------------
extern "C" void kernel_launch(void* const* d_in, const int* in_sizes, int n_in,
                              void* d_out, int out_size) {
    const float* Xtr = (const float*)d_in[0];
    const float* y   = (const float*)d_in[1];
    const float* Xte = (const float*)d_in[2];
    float* out = (float*)d_out;

    cudaFuncSetAttribute(chol_kernel, cudaFuncAttributeMaxDynamicSharedMemorySize, CHOL_DYN);

    prep_kernel<<<N / 256, 256>>>(Xtr, y);
    build_kernel<<<NTASK, 256>>>(Xtr);
    chol_kernel<<<GRID_CHOL, 256, CHOL_DYN>>>();
    fwd_solve<<<NB, 512>>>();
    bwd_solve<<<NB, 512>>>();
    predict_kernel<<<N / 32, 256>>>(Xte, Xtr, out);
}

// round 5
// speedup vs baseline: 1.1274x; 1.0033x over previous
#include <cuda_runtime.h>
#include <math.h>

#define N 8192
#define D 32
#define NB 64
#define B 128
#define GAMMA 0.03125f
#define REG 1e-3f
#define NTASK (NB * (NB + 1) / 2)   // 2080
#define GRID_CHOL 296
#define FBASE(j) ((j) * (2 * NB - (j) + 1) / 2)

// ---------------- device scratch ----------------
__device__ float g_A[(size_t)N * N];
__device__ float g_invL[(size_t)NB * B * B];
__device__ float g_xx[N];
__device__ float g_r[N];
__device__ float g_zsol[N];
__device__ float g_alpha[N];
__device__ int   g_tflag[NTASK];
__device__ int   g_dflag[NB];
__device__ int   g_ff[NB];
__device__ int   g_fb[NB];
__device__ int   g_next;

__device__ __forceinline__ void tri_decode_row(int p, int& ti, int& tj) {
    float pf = sqrtf(8.f * (float)p + 1.f);
    int i = (int)((pf - 1.f) * 0.5f);
    while ((i + 1) * (i + 2) / 2 <= p) i++;
    while (i * (i + 1) / 2 > p) i--;
    ti = i; tj = p - i * (i + 1) / 2;
}

// ---------------- prep ----------------
__global__ void prep_kernel(const float* __restrict__ Xtr, const float* __restrict__ y) {
    int i = blockIdx.x * 256 + threadIdx.x;
    float s = 0.f;
#pragma unroll
    for (int dg = 0; dg < 8; dg++) {
        float4 v = *(const float4*)(Xtr + (size_t)i * D + dg * 4);
        s += v.x * v.x + v.y * v.y + v.z * v.z + v.w * v.w;
    }
    g_xx[i] = s;
    g_r[i] = y[i];
    if (i < NTASK) g_tflag[i] = 0;
    if (i < NB) { g_dflag[i] = 0; g_ff[i] = 0; g_fb[i] = 0; }
    if (i == 0) g_next = 0;
}

// ---------------- build gram (lower triangle of 128-blocks) ----------------
__global__ void __launch_bounds__(256, 2) build_kernel(const float* __restrict__ Xtr) {
    __shared__ float sXi[32 * 132];
    __shared__ float sXj[32 * 132];
    __shared__ float sxxi[128], sxxj[128];
    int tid = threadIdx.x;
    int bi, bj;
    tri_decode_row(blockIdx.x, bi, bj);

#pragma unroll
    for (int i = 0; i < 4; i++) {
        int f = tid + i * 256;
        int r = f >> 3;
        int dg = (f & 7) << 2;
        float4 v = *(const float4*)(Xtr + (size_t)(bi * B + r) * D + dg);
        sXi[(dg + 0) * 132 + r] = v.x; sXi[(dg + 1) * 132 + r] = v.y;
        sXi[(dg + 2) * 132 + r] = v.z; sXi[(dg + 3) * 132 + r] = v.w;
        float4 w = *(const float4*)(Xtr + (size_t)(bj * B + r) * D + dg);
        sXj[(dg + 0) * 132 + r] = w.x; sXj[(dg + 1) * 132 + r] = w.y;
        sXj[(dg + 2) * 132 + r] = w.z; sXj[(dg + 3) * 132 + r] = w.w;
    }
    if (tid < 128) { sxxi[tid] = g_xx[bi * B + tid]; sxxj[tid] = g_xx[bj * B + tid]; }
    __syncthreads();

    int tm = tid >> 4, tn = tid & 15;
    float acc[8][8];
#pragma unroll
    for (int i = 0; i < 8; i++)
#pragma unroll
        for (int j = 0; j < 8; j++) acc[i][j] = 0.f;

#pragma unroll
    for (int d = 0; d < 32; d++) {
        float a[8], b[8];
        *(float4*)(a)     = *(const float4*)(&sXi[d * 132 + tm * 8]);
        *(float4*)(a + 4) = *(const float4*)(&sXi[d * 132 + tm * 8 + 4]);
        *(float4*)(b)     = *(const float4*)(&sXj[d * 132 + tn * 8]);
        *(float4*)(b + 4) = *(const float4*)(&sXj[d * 132 + tn * 8 + 4]);
#pragma unroll
        for (int i = 0; i < 8; i++)
#pragma unroll
            for (int j = 0; j < 8; j++) acc[i][j] += a[i] * b[j];
    }

#pragma unroll
    for (int i = 0; i < 8; i++) {
        int li = tm * 8 + i;
        int gi = bi * B + li;
        float v[8];
#pragma unroll
        for (int j = 0; j < 8; j++) {
            int lj = tn * 8 + j;
            int gj = bj * B + lj;
            float sq = sxxi[li] + sxxj[lj] - 2.f * acc[i][j];
            sq = fmaxf(sq, 0.f);
            float val = __expf(-GAMMA * sq);
            if (gi == gj) val += REG;
            v[j] = val;
        }
        float* cp = g_A + (size_t)gi * N + bj * B + tn * 8;
        *(float4*)(cp)     = make_float4(v[0], v[1], v[2], v[3]);
        *(float4*)(cp + 4) = make_float4(v[4], v[5], v[6], v[7]);
    }
}

// ---------------- persistent DAG cholesky, dynamic work claiming ----------------
#define CHOL_DYN (128 * 132 * 4)

__global__ void __launch_bounds__(256, 2) chol_kernel() {
    extern __shared__ float sD[];
    __shared__ float As[16 * 132];
    __shared__ float Bs[16 * 132];
    __shared__ float invd[128];
    __shared__ float rowbuf[128];
    __shared__ int s_t;

    int tid = threadIdx.x;
    int tm = tid >> 4, tn = tid & 15;
    int lr = tid >> 2;
    int lk = (tid & 3) << 2;

    while (true) {
        if (tid == 0) s_t = atomicAdd(&g_next, 1);
        __syncthreads();
        int t = s_t;
        if (t >= NTASK) break;

        // decode column-major triangular index: t -> (i, j), i >= j
        float disc = (2.f * NB + 1.f) * (2.f * NB + 1.f) - 8.f * (float)t;
        int j = (int)((2.f * NB + 1.f - sqrtf(disc)) * 0.5f);
        if (j > NB - 1) j = NB - 1;
        if (j < 0) j = 0;
        while (j < NB - 1 && FBASE(j + 1) <= t) j++;
        while (FBASE(j) > t) j--;
        int i = j + (t - FBASE(j));
        bool diag = (i == j);

        float acc[8][8];
#pragma unroll
        for (int a = 0; a < 8; a++)
#pragma unroll
            for (int b = 0; b < 8; b++) acc[a][b] = 0.f;

        const float* Ai = g_A + (size_t)(i * B) * N;
        const float* Aj = g_A + (size_t)(j * B) * N;

        // ---- left-looking updates: acc += L(i,k) * L(j,k)^T ----
        for (int k = 0; k < j; k++) {
            if (tid == 0) {
                volatile int* tf = (volatile int*)g_tflag;
                while (tf[i * (i + 1) / 2 + k] == 0) __nanosleep(32);
                if (!diag) while (tf[j * (j + 1) / 2 + k] == 0) __nanosleep(32);
            }
            __syncthreads();
            __threadfence();
            const float* Ak = Ai + (size_t)k * B;
            const float* Bk = Aj + (size_t)k * B;

            for (int kk = 0; kk < 128; kk += 16) {
#pragma unroll
                for (int h = 0; h < 2; h++) {
                    int r = lr + (h << 6);
                    float4 va = *(const float4*)(Ak + (size_t)r * N + kk + lk);
                    As[(lk + 0) * 132 + r] = va.x; As[(lk + 1) * 132 + r] = va.y;
                    As[(lk + 2) * 132 + r] = va.z; As[(lk + 3) * 132 + r] = va.w;
                    if (!diag) {
                        float4 vb = *(const float4*)(Bk + (size_t)r * N + kk + lk);
                        Bs[(lk + 0) * 132 + r] = vb.x; Bs[(lk + 1) * 132 + r] = vb.y;
                        Bs[(lk + 2) * 132 + r] = vb.z; Bs[(lk + 3) * 132 + r] = vb.w;
                    }
                }
                __syncthreads();
                const float* Bsrc = diag ? As : Bs;
#pragma unroll
                for (int k2 = 0; k2 < 16; k2++) {
                    float a[8], b[8];
                    *(float4*)(a)     = *(const float4*)(&As[k2 * 132 + tm * 8]);
                    *(float4*)(a + 4) = *(const float4*)(&As[k2 * 132 + tm * 8 + 4]);
                    *(float4*)(b)     = *(const float4*)(&Bsrc[k2 * 132 + tn * 8]);
                    *(float4*)(b + 4) = *(const float4*)(&Bsrc[k2 * 132 + tn * 8 + 4]);
#pragma unroll
                    for (int x = 0; x < 8; x++)
#pragma unroll
                        for (int y = 0; y < 8; y++) acc[x][y] += a[x] * b[y];
                }
                __syncthreads();
            }
        }

        const float* G = g_A + (size_t)(i * B) * N + (size_t)j * B;

        if (diag) {
            // ---- M = gram - acc into sD (pitch 129) ----
#pragma unroll
            for (int x = 0; x < 8; x++) {
                int r = tm * 8 + x;
#pragma unroll
                for (int y = 0; y < 8; y++) {
                    int c = tn * 8 + y;
                    sD[r * 129 + c] = G[(size_t)r * N + c] - acc[x][y];
                }
            }
            __syncthreads();

            // ---- raw-column cholesky: 1 sync per column ----
            int tr = tid & 31, tj2 = tid >> 5;
            for (int c = 0; c < B - 1; c++) {
                float ipiv = __fdividef(1.f, sD[c * 129 + c]);  // col c frozen
                for (int r = c + 1 + tr; r < B; r += 32) {
                    float a = sD[r * 129 + c] * ipiv;
                    for (int jj = c + 1 + tj2; jj <= r; jj += 8)
                        sD[r * 129 + jj] -= a * sD[jj * 129 + c];
                }
                __syncthreads();
            }
            // finalize: invd + scale columns to L + set diag to invd
            for (int c = tid; c < B; c += 256) invd[c] = rsqrtf(sD[c * 129 + c]);
            __syncthreads();
            for (int idx = tid; idx < B * B; idx += 256) {
                int r = idx >> 7, c = idx & 127;
                if (c < r) sD[r * 129 + c] *= invd[c];
                else if (c == r) sD[r * 129 + c] = invd[c];
            }
            __syncthreads();

            // in-place inverse (strict lower overwritten by W, diag = invd)
            for (int r = 1; r < B; r++) {
                for (int c = tid; c < r; c += 256) rowbuf[c] = sD[r * 129 + c];
                __syncthreads();
                if (tid < r) {
                    int c = tid;
                    float a0 = 0.f, a1 = 0.f, a2 = 0.f, a3 = 0.f;
                    int jj = c;
                    for (; jj + 3 < r; jj += 4) {
                        a0 += rowbuf[jj]     * sD[jj * 129 + c];
                        a1 += rowbuf[jj + 1] * sD[(jj + 1) * 129 + c];
                        a2 += rowbuf[jj + 2] * sD[(jj + 2) * 129 + c];
                        a3 += rowbuf[jj + 3] * sD[(jj + 3) * 129 + c];
                    }
                    for (; jj < r; jj++) a0 += rowbuf[jj] * sD[jj * 129 + c];
                    sD[r * 129 + c] = -invd[r] * ((a0 + a1) + (a2 + a3));
                }
                __syncthreads();
            }
            float* Wout = g_invL + (size_t)j * B * B;
            for (int idx = tid; idx < B * B; idx += 256) {
                int r = idx >> 7, c = idx & 127;
                Wout[idx] = (c <= r) ? sD[r * 129 + c] : 0.f;
            }
            __threadfence();
            __syncthreads();
            if (tid == 0) atomicExch(&g_dflag[j], 1);
        } else {
            // ---- stage M^T into sD ----
#pragma unroll
            for (int y = 0; y < 8; y++) {
                int c = tn * 8 + y;
#pragma unroll
                for (int x = 0; x < 8; x++) {
                    int r = tm * 8 + x;
                    sD[c * 132 + r] = G[(size_t)r * N + c] - acc[x][y];
                }
            }
            if (tid == 0) {
                volatile int* df = (volatile int*)g_dflag;
                while (df[j] == 0) __nanosleep(32);
            }
            __syncthreads();
            __threadfence();

            // ---- trsm: out = M * W^T ----
#pragma unroll
            for (int x = 0; x < 8; x++)
#pragma unroll
                for (int y = 0; y < 8; y++) acc[x][y] = 0.f;

            const float* W = g_invL + (size_t)j * B * B;
            for (int kk = 0; kk < 128; kk += 16) {
#pragma unroll
                for (int h = 0; h < 2; h++) {
                    int r = lr + (h << 6);
                    float4 vb = *(const float4*)(W + (size_t)r * B + kk + lk);
                    Bs[(lk + 0) * 132 + r] = vb.x; Bs[(lk + 1) * 132 + r] = vb.y;
                    Bs[(lk + 2) * 132 + r] = vb.z; Bs[(lk + 3) * 132 + r] = vb.w;
                }
                __syncthreads();
#pragma unroll
                for (int k2 = 0; k2 < 16; k2++) {
                    float a[8], b[8];
                    *(float4*)(a)     = *(const float4*)(&sD[(kk + k2) * 132 + tm * 8]);
                    *(float4*)(a + 4) = *(const float4*)(&sD[(kk + k2) * 132 + tm * 8 + 4]);
                    *(float4*)(b)     = *(const float4*)(&Bs[k2 * 132 + tn * 8]);
                    *(float4*)(b + 4) = *(const float4*)(&Bs[k2 * 132 + tn * 8 + 4]);
#pragma unroll
                    for (int x = 0; x < 8; x++)
#pragma unroll
                        for (int y = 0; y < 8; y++) acc[x][y] += a[x] * b[y];
                }
                __syncthreads();
            }
            float* O = g_A + (size_t)(i * B) * N + (size_t)j * B;
#pragma unroll
            for (int x = 0; x < 8; x++) {
                float* cp = O + (size_t)(tm * 8 + x) * N + tn * 8;
                *(float4*)(cp)     = make_float4(acc[x][0], acc[x][1], acc[x][2], acc[x][3]);
                *(float4*)(cp + 4) = make_float4(acc[x][4], acc[x][5], acc[x][6], acc[x][7]);
            }
            __threadfence();
            __syncthreads();
            if (tid == 0) atomicExch(&g_tflag[i * (i + 1) / 2 + j], 1);
        }
        __syncthreads();
    }
}

// ---------------- spin-chained forward solve (512 thr) ----------------
__global__ void __launch_bounds__(512, 1) fwd_solve() {
    int k = blockIdx.x;
    int tid = threadIdx.x;
    int t = tid & 127, q = tid >> 7;
    __shared__ float svec[128];
    __shared__ float red[512];
    float acc = (q == 0) ? g_r[k * B + t] : 0.f;
    for (int j = 0; j < k; j++) {
        if (tid == 0) { while (((volatile int*)g_ff)[j] == 0) __nanosleep(32); }
        __syncthreads();
        __threadfence();
        if (tid < 128) svec[tid] = g_zsol[j * B + tid];
        __syncthreads();
        const float* Lr = g_A + (size_t)(k * B + t) * N + (size_t)j * B + q * 32;
        float a0 = 0.f, a1 = 0.f;
#pragma unroll
        for (int c = 0; c < 32; c += 8) {
            float4 l0 = *(const float4*)(Lr + c);
            float4 l1 = *(const float4*)(Lr + c + 4);
            int cc = q * 32 + c;
            a0 += l0.x * svec[cc] + l0.y * svec[cc + 1] + l0.z * svec[cc + 2] + l0.w * svec[cc + 3];
            a1 += l1.x * svec[cc + 4] + l1.y * svec[cc + 5] + l1.z * svec[cc + 6] + l1.w * svec[cc + 7];
        }
        acc -= a0 + a1;
        __syncthreads();
    }
    red[q * 128 + t] = acc;
    __syncthreads();
    if (tid < 128) svec[tid] = red[tid] + red[128 + tid] + red[256 + tid] + red[384 + tid];
    __syncthreads();
    // diag apply: z = W * rhs
    const float* Wr = g_invL + (size_t)k * B * B + (size_t)t * B + q * 32;
    float z = 0.f;
#pragma unroll
    for (int c = 0; c < 32; c += 4) {
        float4 w = *(const float4*)(Wr + c);
        int cc = q * 32 + c;
        z += w.x * svec[cc] + w.y * svec[cc + 1] + w.z * svec[cc + 2] + w.w * svec[cc + 3];
    }
    red[q * 128 + t] = z;
    __syncthreads();
    if (tid < 128) g_zsol[k * B + tid] = red[tid] + red[128 + tid] + red[256 + tid] + red[384 + tid];
    __threadfence();
    __syncthreads();
    if (tid == 0) atomicExch(&g_ff[k], 1);
}

// ---------------- spin-chained backward solve (512 thr) ----------------
__global__ void __launch_bounds__(512, 1) bwd_solve() {
    int k = NB - 1 - blockIdx.x;
    int tid = threadIdx.x;
    int t = tid & 127, q = tid >> 7;
    __shared__ float svec[128];
    __shared__ float red[512];
    float acc = (q == 0) ? g_zsol[k * B + t] : 0.f;
    for (int j = k + 1; j < NB; j++) {
        if (tid == 0) { while (((volatile int*)g_fb)[j] == 0) __nanosleep(32); }
        __syncthreads();
        __threadfence();
        if (tid < 128) svec[tid] = g_alpha[j * B + tid];
        __syncthreads();
        const float* Lc = g_A + (size_t)(j * B + q * 32) * N + (size_t)k * B + t;
        float a0 = 0.f, a1 = 0.f, a2 = 0.f, a3 = 0.f;
#pragma unroll
        for (int r = 0; r < 32; r += 4) {
            int rr = q * 32 + r;
            a0 += Lc[(size_t)(r + 0) * N] * svec[rr + 0];
            a1 += Lc[(size_t)(r + 1) * N] * svec[rr + 1];
            a2 += Lc[(size_t)(r + 2) * N] * svec[rr + 2];
            a3 += Lc[(size_t)(r + 3) * N] * svec[rr + 3];
        }
        acc -= ((a0 + a1) + (a2 + a3));
        __syncthreads();
    }
    red[q * 128 + t] = acc;
    __syncthreads();
    if (tid < 128) svec[tid] = red[tid] + red[128 + tid] + red[256 + tid] + red[384 + tid];
    __syncthreads();
    // diag apply: alpha = W^T * rhs
    const float* Wc = g_invL + (size_t)k * B * B + (size_t)(q * 32) * B + t;
    float al = 0.f;
#pragma unroll 8
    for (int r = 0; r < 32; r++) al += Wc[(size_t)r * B] * svec[q * 32 + r];
    red[q * 128 + t] = al;
    __syncthreads();
    if (tid < 128) g_alpha[k * B + tid] = red[tid] + red[128 + tid] + red[256 + tid] + red[384 + tid];
    __threadfence();
    __syncthreads();
    if (tid == 0) atomicExch(&g_fb[k], 1);
}

// ---------------- fused predict ----------------
__global__ void __launch_bounds__(256, 2) predict_kernel(const float* __restrict__ Xte,
                                                         const float* __restrict__ Xtr,
                                                         float* __restrict__ out) {
    __shared__ float sTr[32 * 132];
    __shared__ float sAl[128], sXX[128];
    __shared__ float sRed[256];
    int tid = threadIdx.x;
    int rl = tid >> 3, sl = tid & 7;
    int grow = blockIdx.x * 32 + rl;

    float xt[32];
#pragma unroll
    for (int dg = 0; dg < 8; dg++)
        *(float4*)(xt + dg * 4) = *(const float4*)(Xte + (size_t)grow * D + dg * 4);
    float xxt = 0.f;
#pragma unroll
    for (int d = 0; d < 32; d++) xxt += xt[d] * xt[d];

    float acc = 0.f;
    for (int ch = 0; ch < N / 128; ch++) {
        int pbase = ch * 128;
        __syncthreads();
#pragma unroll
        for (int i = 0; i < 4; i++) {
            int f = tid + i * 256;
            int p = f >> 3;
            int dg = (f & 7) << 2;
            float4 v = *(const float4*)(Xtr + (size_t)(pbase + p) * D + dg);
            sTr[(dg + 0) * 132 + p] = v.x; sTr[(dg + 1) * 132 + p] = v.y;
            sTr[(dg + 2) * 132 + p] = v.z; sTr[(dg + 3) * 132 + p] = v.w;
        }
        if (tid < 128) { sAl[tid] = g_alpha[pbase + tid]; sXX[tid] = g_xx[pbase + tid]; }
        __syncthreads();
#pragma unroll 4
        for (int i = 0; i < 16; i++) {
            int p = i * 8 + sl;
            float dot = 0.f;
#pragma unroll
            for (int d = 0; d < 32; d++) dot += xt[d] * sTr[d * 132 + p];
            float sq = fmaxf(xxt + sXX[p] - 2.f * dot, 0.f);
            acc += __expf(-GAMMA * sq) * sAl[p];
        }
    }
    sRed[rl * 8 + sl] = acc;
    __syncthreads();
    if (tid < 32) {
        float s = 0.f;
#pragma unroll
        for (int j = 0; j < 8; j++) s += sRed[tid * 8 + j];
        out[blockIdx.x * 32 + tid] = s;
    }
}

// ---------------- launcher ----------------
extern "C" void kernel_launch(void* const* d_in, const int* in_sizes, int n_in,
                              void* d_out, int out_size) {
    const float* Xtr = (const float*)d_in[0];
    const float* y   = (const float*)d_in[1];
    const float* Xte = (const float*)d_in[2];
    float* out = (float*)d_out;

    cudaFuncSetAttribute(chol_kernel, cudaFuncAttributeMaxDynamicSharedMemorySize, CHOL_DYN);

    prep_kernel<<<N / 256, 256>>>(Xtr, y);
    build_kernel<<<NTASK, 256>>>(Xtr);
    chol_kernel<<<GRID_CHOL, 256, CHOL_DYN>>>();
    fwd_solve<<<NB, 512>>>();
    bwd_solve<<<NB, 512>>>();
    predict_kernel<<<N / 32, 256>>>(Xte, Xtr, out);
}